// round 1
// baseline (speedup 1.0000x reference)
#include <cuda_runtime.h>
#include <math.h>

// ---------------------------------------------------------------------------
// Mie scattering:
//   1) x_mean = mean(pi*d/lambda)        (deterministic 2-stage reduction)
//   2) a_n, b_n (n=1..50) from x_mean    (double-precision Bessel recurrences)
//      folded into p_n = c_n(a+b)/2, q_n = c_n(a-b)/2
//   3) per-element: A = sum p_n*(pi_n+tau_n), B = sum q_n*(pi_n-tau_n)
//      intensity = (|A|^2+|B|^2) * lambda^2/(4 pi^2)
// ---------------------------------------------------------------------------

#define N_TERMS   50
#define RED_BLOCKS 512
#define RED_THREADS 256

static __device__ double g_partials[RED_BLOCKS];
static __device__ float4 g_pq[N_TERMS];   // (p.re, p.im, q.re, q.im) per n

// ---------------- Stage 1: partial sums of x = pi*d/lambda ------------------
__global__ void mie_reduce_kernel(const float* __restrict__ d, int n) {
    __shared__ double sh[RED_THREADS];
    double acc = 0.0;
    int stride = gridDim.x * blockDim.x;
    for (int i = blockIdx.x * blockDim.x + threadIdx.x; i < n; i += stride) {
        // replicate reference fp32 roundings: (fp32(pi) * d) / fp32(5.5e-7)
        float t = __fmul_rn(3.14159274101257324f, d[i]);
        float x = __fdiv_rn(t, 5.5e-7f);
        acc += (double)x;
    }
    sh[threadIdx.x] = acc;
    __syncthreads();
    for (int s = RED_THREADS / 2; s > 0; s >>= 1) {
        if (threadIdx.x < s) sh[threadIdx.x] += sh[threadIdx.x + s];
        __syncthreads();
    }
    if (threadIdx.x == 0) g_partials[blockIdx.x] = sh[0];
}

// ---------------- Stage 2: finalize mean + Mie coefficients -----------------
__global__ void mie_coeff_kernel(int n_total) {
    __shared__ double sh[64];
    __shared__ double jx[N_TERMS + 1], yx[N_TERMS + 1], jmx[N_TERMS + 1];
    __shared__ double shx, shmx;
    int t = threadIdx.x;

    // deterministic final sum of 512 partials
    double s = 0.0;
    for (int i = t; i < RED_BLOCKS; i += 64) s += g_partials[i];
    sh[t] = s;
    __syncthreads();
    for (int w = 32; w > 0; w >>= 1) {
        if (t < w) sh[t] += sh[t + w];
        __syncthreads();
    }

    if (t == 0) {
        float xmf = (float)(sh[0] / (double)n_total);   // round mean to fp32 (like jnp.mean)
        float mxf = __fmul_rn(1.31f, xmf);              // fp32 m*x as in reference
        double x  = (double)xmf;
        double mx = (double)mxf;
        shx = x; shmx = mx;

        double sx = sin(x),  cx = cos(x);
        double smx = sin(mx), cmx = cos(mx);
        jx[0]  = sx / x;
        jx[1]  = sx / (x * x) - cx / x;
        yx[0]  = -cx / x;
        yx[1]  = -cx / (x * x) - sx / x;
        jmx[0] = smx / mx;
        jmx[1] = smx / (mx * mx) - cmx / mx;
        for (int k = 1; k < N_TERMS; k++) {
            double c  = (2.0 * k + 1.0) / x;
            double cm = (2.0 * k + 1.0) / mx;
            jx[k + 1]  = c  * jx[k]  - jx[k - 1];
            yx[k + 1]  = c  * yx[k]  - yx[k - 1];
            jmx[k + 1] = cm * jmx[k] - jmx[k - 1];
        }
    }
    __syncthreads();

    if (t < N_TERMS) {
        int n = t + 1;
        double dn = (double)n;
        double x = shx, mx = shmx;
        double m = (double)1.31f;

        double jn  = jx[n],  jn1 = jx[n - 1];
        double yn  = yx[n],  yn1 = yx[n - 1];
        double jm  = jmx[n], jm1 = jmx[n - 1];

        double dj = jm1 - (dn + 1.0) / mx * jm;
        double D  = dj / (jm + 1e-10);

        double psi  = x * jn,  psi1 = x * jn1;
        double chi  = x * yn,  chi1 = x * yn1;   // xi = psi + i*chi

        double nx = dn / x;
        double fa = D / m + nx;
        double fb = m * D + nx;

        // a = (fa*psi - psi1) / (fa*xi - xi1 + eps)   (numerator real)
        double numa = fa * psi - psi1;
        double dar  = numa + 1e-10;
        double dai  = fa * chi - chi1;
        double ia   = 1.0 / (dar * dar + dai * dai);
        double ar   = numa * dar * ia;
        double ai   = -numa * dai * ia;

        double numb = fb * psi - psi1;
        double dbr  = numb + 1e-10;
        double dbi  = fb * chi - chi1;
        double ib   = 1.0 / (dbr * dbr + dbi * dbi);
        double br   = numb * dbr * ib;
        double bi   = -numb * dbi * ib;

        double cc = 0.5 * (2.0 * dn + 1.0) / (dn * (dn + 1.0));
        g_pq[t] = make_float4((float)(cc * (ar + br)), (float)(cc * (ai + bi)),
                              (float)(cc * (ar - br)), (float)(cc * (ai - bi)));
    }
}

// ---------------- Stage 3: per-element angular sum --------------------------
__global__ void __launch_bounds__(256) mie_main_kernel(
    const float* __restrict__ theta, float* __restrict__ out, int n)
{
    __shared__ float4 spq[N_TERMS];
    if (threadIdx.x < N_TERMS) spq[threadIdx.x] = g_pq[threadIdx.x];
    __syncthreads();

    int i = blockIdx.x * blockDim.x + threadIdx.x;
    if (i >= n) return;

    float th = theta[i];
    float c  = cosf(th);
    float st = sinf(th) + 1e-10f;
    float inv_s = 1.0f / st;

    float sq  = fmaxf(1.0f - c * c, 0.0f);
    float pi1 = -sqrtf(sq) * inv_s;

    // n = 1: tau_1 = cos(theta)
    float4 w0 = spq[0];
    float u = pi1 + c;
    float v = pi1 - c;
    float Ar = w0.x * u, Ai = w0.y * u;
    float Br = w0.z * v, Bi = w0.w * v;

    float pip = pi1;              // pi_{n-1}
    float pic = 3.0f * c * pi1;   // pi_2 (pi_0 = 0)

#pragma unroll
    for (int n2 = 2; n2 <= N_TERMS; n2++) {
        const float nf   = (float)n2;
        const float np1  = (float)(n2 + 1);
        const float invn = 1.0f / (float)n2;

        float t1 = c * pic;
        float t2 = np1 * pip;
        float ta = fmaf(nf, t1, -t2);          // tau_n
        float uu = pic + ta;
        float vv = pic - ta;

        float4 w = spq[n2 - 1];
        Ar = fmaf(w.x, uu, Ar);
        Ai = fmaf(w.y, uu, Ai);
        Br = fmaf(w.z, vv, Br);
        Bi = fmaf(w.w, vv, Bi);

        float pin = fmaf(np1, t1, ta) * invn;  // pi_{n+1}
        pip = pic;
        pic = pin;
    }

    const float SCALE = (float)(5.5e-7 * 5.5e-7 / (4.0 * 3.14159265358979323846 *
                                                   3.14159265358979323846));
    float inten = Ar * Ar + Ai * Ai + Br * Br + Bi * Bi;  // (|S1|^2+|S2|^2)/2
    out[i] = inten * SCALE;
}

// ---------------------------------------------------------------------------
extern "C" void kernel_launch(void* const* d_in, const int* in_sizes, int n_in,
                              void* d_out, int out_size) {
    const float* d     = (const float*)d_in[0];
    const float* theta = (const float*)d_in[1];
    float* out = (float*)d_out;
    int n = in_sizes[0];

    mie_reduce_kernel<<<RED_BLOCKS, RED_THREADS>>>(d, n);
    mie_coeff_kernel<<<1, 64>>>(n);
    int blocks = (n + 255) / 256;
    mie_main_kernel<<<blocks, 256>>>(theta, out, n);
}

// round 3
// speedup vs baseline: 1.1357x; 1.1357x over previous
#include <cuda_runtime.h>
#include <math.h>

// ---------------------------------------------------------------------------
// Mie scattering via Chebyshev/Clenshaw:
//   1) x_mean = mean(pi*d/lambda)        (float4 loads, fp32 chunk accumulate,
//                                         deterministic double finalize)
//   2) coeff kernel: a_n,b_n in double; then convert the angular sum
//      S1,S2 into TWO complex degree-50 polynomials A(c), B(c) in the
//      CHEBYSHEV basis (coeffs alpha_k), in double, parallel over k.
//   3) main kernel: per element, evaluate A(c), B(c) by Clenshaw with
//      packed fma.rn.f32x2 ((re,im) in one 64-bit reg), 4 elems/thread.
//      intensity = (|A|^2+|B|^2) * lambda^2/(4 pi^2)
// ---------------------------------------------------------------------------

#define N_TERMS    50
#define RED_BLOCKS 512
#define RED_THREADS 256

static __device__ double g_partials[RED_BLOCKS];
static __device__ float4 g_cheb[N_TERMS + 1];   // (A.re, A.im, B.re, B.im) per k

typedef unsigned long long ull;

// ---------------- packed f32x2 helpers --------------------------------------
__device__ __forceinline__ ull pk2(float lo, float hi) {
    ull r; asm("mov.b64 %0, {%1, %2};" : "=l"(r) : "f"(lo), "f"(hi)); return r;
}
__device__ __forceinline__ void upk2(ull v, float& lo, float& hi) {
    asm("mov.b64 {%0, %1}, %2;" : "=f"(lo), "=f"(hi) : "l"(v));
}
__device__ __forceinline__ ull fma2_(ull a, ull b, ull c) {
    ull d; asm("fma.rn.f32x2 %0, %1, %2, %3;" : "=l"(d) : "l"(a), "l"(b), "l"(c));
    return d;
}

// ---------------- Stage 1: partial sums of x = pi*d/lambda ------------------
__global__ void mie_reduce_kernel(const float* __restrict__ d, int n) {
    __shared__ double sh[RED_THREADS];
    float a0 = 0.f, a1 = 0.f, a2 = 0.f, a3 = 0.f;
    int n4 = n >> 2;
    const float4* __restrict__ d4 = (const float4*)d;
    int stride = gridDim.x * blockDim.x;
    for (int i = blockIdx.x * blockDim.x + threadIdx.x; i < n4; i += stride) {
        float4 v = d4[i];
        // replicate reference fp32 roundings: (fp32(pi) * d) / fp32(5.5e-7)
        a0 += __fdiv_rn(__fmul_rn(3.14159274101257324f, v.x), 5.5e-7f);
        a1 += __fdiv_rn(__fmul_rn(3.14159274101257324f, v.y), 5.5e-7f);
        a2 += __fdiv_rn(__fmul_rn(3.14159274101257324f, v.z), 5.5e-7f);
        a3 += __fdiv_rn(__fmul_rn(3.14159274101257324f, v.w), 5.5e-7f);
    }
    // scalar tail (benchmark shape is divisible by 4; kept for generality)
    int tail_start = n4 << 2;
    for (int i = tail_start + blockIdx.x * blockDim.x + threadIdx.x; i < n;
         i += stride)
        a0 += __fdiv_rn(__fmul_rn(3.14159274101257324f, d[i]), 5.5e-7f);

    double acc = ((double)a0 + (double)a1) + ((double)a2 + (double)a3);
    sh[threadIdx.x] = acc;
    __syncthreads();
    for (int s = RED_THREADS / 2; s > 0; s >>= 1) {
        if (threadIdx.x < s) sh[threadIdx.x] += sh[threadIdx.x + s];
        __syncthreads();
    }
    if (threadIdx.x == 0) g_partials[blockIdx.x] = sh[0];
}

// ---------------- Stage 2: mean + Mie coeffs + Chebyshev conversion ---------
__global__ void mie_coeff_kernel(int n_total) {
    __shared__ double sh[64];
    __shared__ double jx[N_TERMS + 1], yx[N_TERMS + 1], jmx[N_TERMS + 1];
    __shared__ double shx, shmx;
    __shared__ double pR[N_TERMS], pI[N_TERMS], qR[N_TERMS], qI[N_TERMS];
    __shared__ double Pp[N_TERMS + 2], Pc[N_TERMS + 2];  // pi_{n-1}, pi_n coeffs
    int t = threadIdx.x;

    // deterministic final sum of partials
    double s = 0.0;
    for (int i = t; i < RED_BLOCKS; i += 64) s += g_partials[i];
    sh[t] = s;
    __syncthreads();
    for (int w = 32; w > 0; w >>= 1) {
        if (t < w) sh[t] += sh[t + w];
        __syncthreads();
    }

    if (t == 0) {
        float xmf = (float)(sh[0] / (double)n_total);   // fp32 mean like jnp
        float mxf = __fmul_rn(1.31f, xmf);              // fp32 m*x
        double x  = (double)xmf;
        double mx = (double)mxf;
        shx = x; shmx = mx;

        double sx = sin(x),  cx = cos(x);
        double smx = sin(mx), cmx = cos(mx);
        jx[0]  = sx / x;
        jx[1]  = sx / (x * x) - cx / x;
        yx[0]  = -cx / x;
        yx[1]  = -cx / (x * x) - sx / x;
        jmx[0] = smx / mx;
        jmx[1] = smx / (mx * mx) - cmx / mx;
        for (int k = 1; k < N_TERMS; k++) {
            double c  = (2.0 * k + 1.0) / x;
            double cm = (2.0 * k + 1.0) / mx;
            jx[k + 1]  = c  * jx[k]  - jx[k - 1];
            yx[k + 1]  = c  * yx[k]  - yx[k - 1];
            jmx[k + 1] = cm * jmx[k] - jmx[k - 1];
        }
    }
    __syncthreads();

    if (t < N_TERMS) {
        int n = t + 1;
        double dn = (double)n;
        double x = shx, mx = shmx;
        double m = (double)1.31f;

        double jn  = jx[n],  jn1 = jx[n - 1];
        double yn  = yx[n],  yn1 = yx[n - 1];
        double jm  = jmx[n], jm1 = jmx[n - 1];

        double dj = jm1 - (dn + 1.0) / mx * jm;
        double D  = dj / (jm + 1e-10);

        double psi  = x * jn,  psi1 = x * jn1;
        double chi  = x * yn,  chi1 = x * yn1;   // xi = psi + i*chi

        double nx = dn / x;
        double fa = D / m + nx;
        double fb = m * D + nx;

        double numa = fa * psi - psi1;
        double dar  = numa + 1e-10;
        double dai  = fa * chi - chi1;
        double ia   = 1.0 / (dar * dar + dai * dai);
        double ar   = numa * dar * ia;
        double ai   = -numa * dai * ia;

        double numb = fb * psi - psi1;
        double dbr  = numb + 1e-10;
        double dbi  = fb * chi - chi1;
        double ib   = 1.0 / (dbr * dbr + dbi * dbi);
        double br   = numb * dbr * ib;
        double bi   = -numb * dbi * ib;

        double cc = 0.5 * (2.0 * dn + 1.0) / (dn * (dn + 1.0));
        pR[t] = cc * (ar + br);  pI[t] = cc * (ai + bi);
        qR[t] = cc * (ar - br);  qI[t] = cc * (ai - bi);
    }

    // init Chebyshev coefficient arrays for pi_0 = 0, pi_1 = -1 (ref sign)
    if (t < N_TERMS + 2) { Pp[t] = 0.0; Pc[t] = 0.0; }
    __syncthreads();
    if (t == 0) Pc[0] = -1.0;
    __syncthreads();

    // Chebyshev-space recurrence, thread t owns coefficient index k = t
    double AcR = 0.0, AcI = 0.0, BcR = 0.0, BcI = 0.0;
    int k = t;
    for (int n = 1; n <= N_TERMS; n++) {
        double cpk = 0.0, tauk = 0.0, pnext = 0.0, u = 0.0, v = 0.0;
        if (k <= N_TERMS) {
            // coefficients of c * pi_n in Chebyshev basis
            if (k == 0)      cpk = 0.5 * Pc[1];
            else if (k == 1) cpk = Pc[0] + 0.5 * Pc[2];
            else             cpk = 0.5 * (Pc[k - 1] + Pc[k + 1]);

            double dn = (double)n;
            if (n == 1) tauk = (k == 1) ? 1.0 : 0.0;   // reference: tau_1 = +c
            else        tauk = dn * cpk - (dn + 1.0) * Pp[k];

            u = Pc[k] + tauk;
            v = Pc[k] - tauk;
            AcR += pR[n - 1] * u;  AcI += pI[n - 1] * u;
            BcR += qR[n - 1] * v;  BcI += qI[n - 1] * v;

            pnext = ((2.0 * dn + 1.0) * cpk - (dn + 1.0) * Pp[k]) / dn;
        }
        __syncthreads();
        if (k <= N_TERMS) { Pp[k] = Pc[k]; Pc[k] = pnext; }
        __syncthreads();
    }

    if (k <= N_TERMS)
        g_cheb[k] = make_float4((float)AcR, (float)AcI, (float)BcR, (float)BcI);
}

// ---------------- Stage 3: Clenshaw evaluation per element ------------------
#define ELEMS_PER_THREAD 4

__global__ void __launch_bounds__(256) mie_main_kernel(
    const float* __restrict__ theta, float* __restrict__ out, int n)
{
    __shared__ float4 sc[N_TERMS + 1];
    if (threadIdx.x <= N_TERMS) sc[threadIdx.x] = g_cheb[threadIdx.x];
    __syncthreads();

    const float SCALE = (float)(5.5e-7 * 5.5e-7 /
        (4.0 * 3.14159265358979323846 * 3.14159265358979323846));
    const ull NEG1 = pk2(-1.0f, -1.0f);

    long long base = (long long)(blockIdx.x * blockDim.x + threadIdx.x) *
                     ELEMS_PER_THREAD;

    if (base + ELEMS_PER_THREAD <= n) {
        float4 th4 = *(const float4*)(theta + base);
        float cs[4];
        cs[0] = cosf(th4.x); cs[1] = cosf(th4.y);
        cs[2] = cosf(th4.z); cs[3] = cosf(th4.w);

        ull t2[4], bA1[4], bA2[4], bB1[4], bB2[4];
#pragma unroll
        for (int e = 0; e < 4; e++) {
            float tt = cs[e] + cs[e];
            t2[e] = pk2(tt, tt);
            bA1[e] = 0ull; bA2[e] = 0ull; bB1[e] = 0ull; bB2[e] = 0ull;
        }

#pragma unroll
        for (int kk = N_TERMS; kk >= 1; kk--) {
            const ulonglong2 al = *(const ulonglong2*)&sc[kk]; // (A.re,A.im),(B.re,B.im)
#pragma unroll
            for (int e = 0; e < 4; e++) {
                ull tA = fma2_(NEG1, bA2[e], al.x);     // alpha - b2
                ull nA = fma2_(t2[e], bA1[e], tA);      // b = 2c*b1 + (alpha-b2)
                bA2[e] = bA1[e]; bA1[e] = nA;
                ull tB = fma2_(NEG1, bB2[e], al.y);
                ull nB = fma2_(t2[e], bB1[e], tB);
                bB2[e] = bB1[e]; bB1[e] = nB;
            }
        }

        const ulonglong2 al0 = *(const ulonglong2*)&sc[0];
        float4 res;
        float* resp = (float*)&res;
#pragma unroll
        for (int e = 0; e < 4; e++) {
            ull c2 = pk2(cs[e], cs[e]);
            ull fA = fma2_(c2, bA1[e], fma2_(NEG1, bA2[e], al0.x));
            ull fB = fma2_(c2, bB1[e], fma2_(NEG1, bB2[e], al0.y));
            float Ar, Ai, Br, Bi;
            upk2(fA, Ar, Ai);
            upk2(fB, Br, Bi);
            float inten = fmaf(Ar, Ar, fmaf(Ai, Ai, fmaf(Br, Br, Bi * Bi)));
            resp[e] = inten * SCALE;
        }
        *(float4*)(out + base) = res;
    } else {
        // scalar tail (not hit for the benchmark shape)
        for (long long i = base; i < n && i < base + ELEMS_PER_THREAD; i++) {
            float c = cosf(theta[i]);
            float tt = c + c;
            float bA1r = 0.f, bA1i = 0.f, bA2r = 0.f, bA2i = 0.f;
            float bB1r = 0.f, bB1i = 0.f, bB2r = 0.f, bB2i = 0.f;
            for (int kk = N_TERMS; kk >= 1; kk--) {
                float4 a = sc[kk];
                float nAr = fmaf(tt, bA1r, a.x - bA2r);
                float nAi = fmaf(tt, bA1i, a.y - bA2i);
                float nBr = fmaf(tt, bB1r, a.z - bB2r);
                float nBi = fmaf(tt, bB1i, a.w - bB2i);
                bA2r = bA1r; bA2i = bA1i; bA1r = nAr; bA1i = nAi;
                bB2r = bB1r; bB2i = bB1i; bB1r = nBr; bB1i = nBi;
            }
            float4 a0 = sc[0];
            float Ar = fmaf(c, bA1r, a0.x - bA2r);
            float Ai = fmaf(c, bA1i, a0.y - bA2i);
            float Br = fmaf(c, bB1r, a0.z - bB2r);
            float Bi = fmaf(c, bB1i, a0.w - bB2i);
            float inten = fmaf(Ar, Ar, fmaf(Ai, Ai, fmaf(Br, Br, Bi * Bi)));
            out[i] = inten * SCALE;
        }
    }
}

// ---------------------------------------------------------------------------
extern "C" void kernel_launch(void* const* d_in, const int* in_sizes, int n_in,
                              void* d_out, int out_size) {
    const float* d     = (const float*)d_in[0];
    const float* theta = (const float*)d_in[1];
    float* out = (float*)d_out;
    int n = in_sizes[0];

    mie_reduce_kernel<<<RED_BLOCKS, RED_THREADS>>>(d, n);
    mie_coeff_kernel<<<1, 64>>>(n);
    int threads_needed = (n + ELEMS_PER_THREAD - 1) / ELEMS_PER_THREAD;
    int blocks = (threads_needed + 255) / 256;
    mie_main_kernel<<<blocks, 256>>>(theta, out, n);
}

// round 5
// speedup vs baseline: 2.3489x; 2.0682x over previous
#include <cuda_runtime.h>
#include <math.h>

// ---------------------------------------------------------------------------
// Mie scattering, table-based:
//   1) reduce:  x_mean partials (float4 x8 unrolled, deterministic)
//   2) coeff:   a_n,b_n in double from x_mean -> folded p_n,q_n (double4)
//   3) table:   I(theta) on uniform 8192-interval grid, full double-precision
//               reference recurrence per grid point
//   4) main:    per element, cubic Lagrange interpolation from smem table
// ---------------------------------------------------------------------------

#define N_TERMS    50
#define RED_BLOCKS 576
#define RED_THREADS 256
#define TABLE_N    8192                 // intervals over [0, pi]
#define TABLE_PTS  (TABLE_N + 4)        // padded points 0..8195
#define ELEMS_PER_BLOCK (256 * 32)      // 8192 elems / block in main

static __device__ double  g_partials[RED_BLOCKS];
static __device__ double4 g_pqd[N_TERMS];     // (p.re, p.im, q.re, q.im)
static __device__ float   g_table[TABLE_PTS];

// ---------------- Stage 1: partial sums of x = pi*d/lambda ------------------
__global__ void mie_reduce_kernel(const float* __restrict__ d, int n) {
    __shared__ double sh[RED_THREADS];
    float a0 = 0.f, a1 = 0.f, a2 = 0.f, a3 = 0.f;
    int n4 = n >> 2;
    const float4* __restrict__ d4 = (const float4*)d;
    int T   = gridDim.x * blockDim.x;
    int gid = blockIdx.x * blockDim.x + threadIdx.x;

    if (n4 == T * 8) {                 // benchmark shape: exactly 8 float4/thread
#pragma unroll
        for (int k = 0; k < 8; k++) {
            float4 v = d4[gid + k * T];
            a0 += __fdiv_rn(__fmul_rn(3.14159274101257324f, v.x), 5.5e-7f);
            a1 += __fdiv_rn(__fmul_rn(3.14159274101257324f, v.y), 5.5e-7f);
            a2 += __fdiv_rn(__fmul_rn(3.14159274101257324f, v.z), 5.5e-7f);
            a3 += __fdiv_rn(__fmul_rn(3.14159274101257324f, v.w), 5.5e-7f);
        }
    } else {
        for (int i = gid; i < n4; i += T) {
            float4 v = d4[i];
            a0 += __fdiv_rn(__fmul_rn(3.14159274101257324f, v.x), 5.5e-7f);
            a1 += __fdiv_rn(__fmul_rn(3.14159274101257324f, v.y), 5.5e-7f);
            a2 += __fdiv_rn(__fmul_rn(3.14159274101257324f, v.z), 5.5e-7f);
            a3 += __fdiv_rn(__fmul_rn(3.14159274101257324f, v.w), 5.5e-7f);
        }
        for (int i = (n4 << 2) + gid; i < n; i += T)
            a0 += __fdiv_rn(__fmul_rn(3.14159274101257324f, d[i]), 5.5e-7f);
    }

    sh[threadIdx.x] = ((double)a0 + (double)a1) + ((double)a2 + (double)a3);
    __syncthreads();
    for (int s = RED_THREADS / 2; s > 0; s >>= 1) {
        if (threadIdx.x < s) sh[threadIdx.x] += sh[threadIdx.x + s];
        __syncthreads();
    }
    if (threadIdx.x == 0) g_partials[blockIdx.x] = sh[0];
}

// ---------------- Stage 2: mean + Mie coefficients (double) -----------------
__global__ void mie_coeff_kernel(int n_total) {
    __shared__ double sh[64];
    __shared__ double jx[N_TERMS + 1], yx[N_TERMS + 1], jmx[N_TERMS + 1];
    __shared__ double shx, shmx;
    int t = threadIdx.x;

    double s = 0.0;
    for (int i = t; i < RED_BLOCKS; i += 64) s += g_partials[i];
    sh[t] = s;
    __syncthreads();
    for (int w = 32; w > 0; w >>= 1) {
        if (t < w) sh[t] += sh[t + w];
        __syncthreads();
    }

    if (t == 0) {
        float xmf = (float)(sh[0] / (double)n_total);   // fp32 mean like jnp
        float mxf = __fmul_rn(1.31f, xmf);              // fp32 m*x
        double x  = (double)xmf;
        double mx = (double)mxf;
        shx = x; shmx = mx;

        double sx = sin(x),  cx = cos(x);
        double smx = sin(mx), cmx = cos(mx);
        jx[0]  = sx / x;
        jx[1]  = sx / (x * x) - cx / x;
        yx[0]  = -cx / x;
        yx[1]  = -cx / (x * x) - sx / x;
        jmx[0] = smx / mx;
        jmx[1] = smx / (mx * mx) - cmx / mx;
        for (int k = 1; k < N_TERMS; k++) {
            double c  = (2.0 * k + 1.0) / x;
            double cm = (2.0 * k + 1.0) / mx;
            jx[k + 1]  = c  * jx[k]  - jx[k - 1];
            yx[k + 1]  = c  * yx[k]  - yx[k - 1];
            jmx[k + 1] = cm * jmx[k] - jmx[k - 1];
        }
    }
    __syncthreads();

    if (t < N_TERMS) {
        int n = t + 1;
        double dn = (double)n;
        double x = shx, mx = shmx;
        double m = (double)1.31f;

        double jn  = jx[n],  jn1 = jx[n - 1];
        double yn  = yx[n],  yn1 = yx[n - 1];
        double jm  = jmx[n], jm1 = jmx[n - 1];

        double dj = jm1 - (dn + 1.0) / mx * jm;
        double D  = dj / (jm + 1e-10);

        double psi  = x * jn,  psi1 = x * jn1;
        double chi  = x * yn,  chi1 = x * yn1;   // xi = psi + i*chi

        double nx = dn / x;
        double fa = D / m + nx;
        double fb = m * D + nx;

        double numa = fa * psi - psi1;
        double dar  = numa + 1e-10;
        double dai  = fa * chi - chi1;
        double ia   = 1.0 / (dar * dar + dai * dai);
        double ar   = numa * dar * ia;
        double ai   = -numa * dai * ia;

        double numb = fb * psi - psi1;
        double dbr  = numb + 1e-10;
        double dbi  = fb * chi - chi1;
        double ib   = 1.0 / (dbr * dbr + dbi * dbi);
        double br   = numb * dbr * ib;
        double bi   = -numb * dbi * ib;

        double cc = 0.5 * (2.0 * dn + 1.0) / (dn * (dn + 1.0));
        g_pqd[t] = make_double4(cc * (ar + br), cc * (ai + bi),
                                cc * (ar - br), cc * (ai - bi));
    }
}

// ---------------- Stage 3: build I(theta) table (double) --------------------
__global__ void mie_table_kernel() {
    int i = blockIdx.x * blockDim.x + threadIdx.x;
    if (i >= TABLE_PTS) return;

    const double H = 3.14159265358979323846 / (double)TABLE_N;
    double th = (double)i * H;
    double c  = cos(th);
    double st = sin(th) + 1e-10;
    double q1 = -sqrt(fmax(1.0 - c * c, 0.0)) / st;   // pi_1 (ref sign)

    // n = 1: tau_1 = c (reference's where-branch)
    double4 w = g_pqd[0];
    double u = q1 + c, v = q1 - c;
    double Ar = w.x * u, Ai = w.y * u;
    double Br = w.z * v, Bi = w.w * v;

    double qp = q1;                // q_{n-1}
    double qc = 3.0 * c * q1;      // q_2  (q_0 = 0)

    for (int n = 2; n <= N_TERMS; n++) {
        double dn = (double)n;
        double tau = dn * c * qc - (dn + 1.0) * qp;
        u = qc + tau; v = qc - tau;
        w = g_pqd[n - 1];
        Ar += w.x * u;  Ai += w.y * u;
        Br += w.z * v;  Bi += w.w * v;
        double qn = ((2.0 * dn + 1.0) * c * qc - (dn + 1.0) * qp) / dn;
        qp = qc; qc = qn;
    }

    const double SCALE = 5.5e-7 * 5.5e-7 /
        (4.0 * 3.14159265358979323846 * 3.14159265358979323846);
    g_table[i] = (float)((Ar * Ar + Ai * Ai + Br * Br + Bi * Bi) * SCALE);
}

// ---------------- Stage 4: cubic Lagrange interpolation ---------------------
__device__ __forceinline__ float interp_cubic(const float* __restrict__ T,
                                              float th, float inv_h) {
    float t  = th * inv_h;
    float jf = floorf(t);
    float s  = t - jf;
    int j = (int)jf - 1;
    j = min(max(j, 0), TABLE_N);          // j+3 <= TABLE_PTS-1

    float sm1 = s + 1.0f, s1 = s - 1.0f, s2 = s - 2.0f;
    float a = s * s1;                      // s(s-1)
    float b = sm1 * s2;                    // (s+1)(s-2)
    float w0 = -0.16666667f * (a * s2);    // -s(s-1)(s-2)/6
    float w1 =  0.5f        * (b * s1);    //  (s+1)(s-1)(s-2)/2
    float w2 = -0.5f        * (b * s);     // -(s+1)s(s-2)/2
    float w3 =  0.16666667f * (sm1 * a);   //  (s+1)s(s-1)/6
    return fmaf(w0, T[j],
           fmaf(w1, T[j + 1],
           fmaf(w2, T[j + 2], w3 * T[j + 3])));
}

__global__ void __launch_bounds__(256) mie_main_kernel(
    const float* __restrict__ theta, float* __restrict__ out, int n)
{
    __shared__ float Ts[TABLE_PTS];
    for (int i = threadIdx.x; i < TABLE_PTS; i += 256)
        Ts[i] = g_table[i];
    __syncthreads();

    const float INV_H = (float)TABLE_N / 3.14159265358979323846f;
    long long blockBase4 = (long long)blockIdx.x * (ELEMS_PER_BLOCK / 4);
    const float4* __restrict__ th4 = (const float4*)theta;
    float4* __restrict__ out4 = (float4*)out;

#pragma unroll
    for (int k = 0; k < 8; k++) {
        long long i4 = blockBase4 + k * 256 + threadIdx.x;
        long long e0 = i4 * 4;
        if (e0 + 3 < n) {
            float4 v = th4[i4];
            float4 r;
            r.x = interp_cubic(Ts, v.x, INV_H);
            r.y = interp_cubic(Ts, v.y, INV_H);
            r.z = interp_cubic(Ts, v.z, INV_H);
            r.w = interp_cubic(Ts, v.w, INV_H);
            out4[i4] = r;
        } else {
            for (long long e = e0; e < n && e < e0 + 4; e++)
                out[e] = interp_cubic(Ts, theta[e], INV_H);
        }
    }
}

// ---------------------------------------------------------------------------
extern "C" void kernel_launch(void* const* d_in, const int* in_sizes, int n_in,
                              void* d_out, int out_size) {
    const float* d     = (const float*)d_in[0];
    const float* theta = (const float*)d_in[1];
    float* out = (float*)d_out;
    int n = in_sizes[0];

    mie_reduce_kernel<<<RED_BLOCKS, RED_THREADS>>>(d, n);
    mie_coeff_kernel<<<1, 64>>>(n);
    mie_table_kernel<<<(TABLE_PTS + 255) / 256, 256>>>();
    int blocks = (n + ELEMS_PER_BLOCK - 1) / ELEMS_PER_BLOCK;
    mie_main_kernel<<<blocks, 256>>>(theta, out, n);
}

// round 7
// speedup vs baseline: 4.3660x; 1.8587x over previous
#include <cuda_runtime.h>
#include <math.h>

// ---------------------------------------------------------------------------
// Mie scattering, table-based v2:
//   1) reduce:  x_mean partials (float4 x8 unrolled, deterministic)
//   2) coeff:   a_n,b_n in double (reciprocal-multiply recurrences) ->
//               folded fp32 p_n,q_n
//   3) table:   I(theta) on 2048-interval grid, fp32 reference recurrence
//   4) main:    cubic Lagrange from float4-packed smem table (1 LDS.128/elem)
// ---------------------------------------------------------------------------

#define N_TERMS    50
#define RED_BLOCKS 576
#define RED_THREADS 256
#define TABLE_N    2048                 // intervals over [0, pi]
#define TABLE_PTS  (TABLE_N + 4)        // scalar points 0..2051
#define TABLE_ENTRIES (TABLE_N + 1)     // float4 entries 0..2048
#define ELEMS_PER_BLOCK (256 * 32)      // 8192 elems / block in main

static __device__ double g_partials[RED_BLOCKS];
static __device__ float4 g_pq[N_TERMS];      // fp32 (p.re, p.im, q.re, q.im)
static __device__ float  g_table[TABLE_PTS];

// ---------------- Stage 1: partial sums of x = pi*d/lambda ------------------
__global__ void mie_reduce_kernel(const float* __restrict__ d, int n) {
    __shared__ double sh[RED_THREADS];
    float a0 = 0.f, a1 = 0.f, a2 = 0.f, a3 = 0.f;
    int n4 = n >> 2;
    const float4* __restrict__ d4 = (const float4*)d;
    int T   = gridDim.x * blockDim.x;
    int gid = blockIdx.x * blockDim.x + threadIdx.x;

    if (n4 == T * 8) {                 // benchmark shape: exactly 8 float4/thread
#pragma unroll
        for (int k = 0; k < 8; k++) {
            float4 v = d4[gid + k * T];
            a0 += __fdiv_rn(__fmul_rn(3.14159274101257324f, v.x), 5.5e-7f);
            a1 += __fdiv_rn(__fmul_rn(3.14159274101257324f, v.y), 5.5e-7f);
            a2 += __fdiv_rn(__fmul_rn(3.14159274101257324f, v.z), 5.5e-7f);
            a3 += __fdiv_rn(__fmul_rn(3.14159274101257324f, v.w), 5.5e-7f);
        }
    } else {
        for (int i = gid; i < n4; i += T) {
            float4 v = d4[i];
            a0 += __fdiv_rn(__fmul_rn(3.14159274101257324f, v.x), 5.5e-7f);
            a1 += __fdiv_rn(__fmul_rn(3.14159274101257324f, v.y), 5.5e-7f);
            a2 += __fdiv_rn(__fmul_rn(3.14159274101257324f, v.z), 5.5e-7f);
            a3 += __fdiv_rn(__fmul_rn(3.14159274101257324f, v.w), 5.5e-7f);
        }
        for (int i = (n4 << 2) + gid; i < n; i += T)
            a0 += __fdiv_rn(__fmul_rn(3.14159274101257324f, d[i]), 5.5e-7f);
    }

    sh[threadIdx.x] = ((double)a0 + (double)a1) + ((double)a2 + (double)a3);
    __syncthreads();
    for (int s = RED_THREADS / 2; s > 0; s >>= 1) {
        if (threadIdx.x < s) sh[threadIdx.x] += sh[threadIdx.x + s];
        __syncthreads();
    }
    if (threadIdx.x == 0) g_partials[blockIdx.x] = sh[0];
}

// ---------------- Stage 2: mean + Mie coefficients (double, no div chain) ---
__global__ void mie_coeff_kernel(int n_total) {
    __shared__ double sh[64];
    __shared__ double jx[N_TERMS + 1], yx[N_TERMS + 1], jmx[N_TERMS + 1];
    __shared__ double shx, shmx, sinvx, sinvmx;
    int t = threadIdx.x;

    double s = 0.0;
    for (int i = t; i < RED_BLOCKS; i += 64) s += g_partials[i];
    sh[t] = s;
    __syncthreads();
    for (int w = 32; w > 0; w >>= 1) {
        if (t < w) sh[t] += sh[t + w];
        __syncthreads();
    }

    if (t == 0) {
        float xmf = (float)(sh[0] / (double)n_total);   // fp32 mean like jnp
        float mxf = __fmul_rn(1.31f, xmf);              // fp32 m*x
        double x  = (double)xmf;
        double mx = (double)mxf;
        double invx  = 1.0 / x;          // hoisted: only 2 fp64 divides here
        double invmx = 1.0 / mx;
        shx = x; shmx = mx; sinvx = invx; sinvmx = invmx;

        double sx = sin(x),  cx = cos(x);
        double smx = sin(mx), cmx = cos(mx);
        jx[0]  = sx * invx;
        jx[1]  = sx * invx * invx - cx * invx;
        yx[0]  = -cx * invx;
        yx[1]  = -cx * invx * invx - sx * invx;
        jmx[0] = smx * invmx;
        jmx[1] = smx * invmx * invmx - cmx * invmx;
        for (int k = 1; k < N_TERMS; k++) {
            double c  = (2.0 * k + 1.0) * invx;
            double cm = (2.0 * k + 1.0) * invmx;
            jx[k + 1]  = c  * jx[k]  - jx[k - 1];
            yx[k + 1]  = c  * yx[k]  - yx[k - 1];
            jmx[k + 1] = cm * jmx[k] - jmx[k - 1];
        }
    }
    __syncthreads();

    if (t < N_TERMS) {
        int n = t + 1;
        double dn = (double)n;
        double x = shx, invx = sinvx, invmx = sinvmx;
        double m = (double)1.31f;

        double jn  = jx[n],  jn1 = jx[n - 1];
        double yn  = yx[n],  yn1 = yx[n - 1];
        double jm  = jmx[n], jm1 = jmx[n - 1];

        double dj = jm1 - (dn + 1.0) * invmx * jm;
        double D  = dj / (jm + 1e-10);

        double psi  = x * jn,  psi1 = x * jn1;
        double chi  = x * yn,  chi1 = x * yn1;   // xi = psi + i*chi

        double nx = dn * invx;
        double fa = D / m + nx;
        double fb = m * D + nx;

        double numa = fa * psi - psi1;
        double dar  = numa + 1e-10;
        double dai  = fa * chi - chi1;
        double ia   = 1.0 / (dar * dar + dai * dai);
        double ar   = numa * dar * ia;
        double ai   = -numa * dai * ia;

        double numb = fb * psi - psi1;
        double dbr  = numb + 1e-10;
        double dbi  = fb * chi - chi1;
        double ib   = 1.0 / (dbr * dbr + dbi * dbi);
        double br   = numb * dbr * ib;
        double bi   = -numb * dbi * ib;

        double cc = 0.5 * (2.0 * dn + 1.0) / (dn * (dn + 1.0));
        g_pq[t] = make_float4((float)(cc * (ar + br)), (float)(cc * (ai + bi)),
                              (float)(cc * (ar - br)), (float)(cc * (ai - bi)));
    }
}

// ---------------- Stage 3: build I(theta) table (fp32 recurrence) -----------
__global__ void mie_table_kernel() {
    int i = blockIdx.x * blockDim.x + threadIdx.x;
    if (i >= TABLE_PTS) return;

    const double H = 3.14159265358979323846 / (double)TABLE_N;
    double thd = (double)i * H;
    float c  = (float)cos(thd);
    float st = (float)sin(thd) + 1e-10f;
    float inv_s = 1.0f / st;
    float pi1 = -sqrtf(fmaxf(1.0f - c * c, 0.0f)) * inv_s;

    // n = 1: tau_1 = c (reference's where-branch)
    float4 w = g_pq[0];
    float u = pi1 + c, v = pi1 - c;
    float Ar = w.x * u, Ai = w.y * u;
    float Br = w.z * v, Bi = w.w * v;

    float qp = pi1;               // pi_{n-1}
    float qc = 3.0f * c * pi1;    // pi_2  (pi_0 = 0)

#pragma unroll
    for (int n = 2; n <= N_TERMS; n++) {
        const float nf   = (float)n;
        const float np1  = (float)(n + 1);
        const float invn = 1.0f / (float)n;   // compile-time constant

        float t1 = c * qc;
        float ta = fmaf(nf, t1, -np1 * qp);   // tau_n
        float uu = qc + ta;
        float vv = qc - ta;

        w = g_pq[n - 1];
        Ar = fmaf(w.x, uu, Ar);
        Ai = fmaf(w.y, uu, Ai);
        Br = fmaf(w.z, vv, Br);
        Bi = fmaf(w.w, vv, Bi);

        float qn = fmaf(np1, t1, ta) * invn;  // pi_{n+1}
        qp = qc; qc = qn;
    }

    const float SCALE = (float)(5.5e-7 * 5.5e-7 /
        (4.0 * 3.14159265358979323846 * 3.14159265358979323846));
    g_table[i] = (Ar * Ar + Ai * Ai + Br * Br + Bi * Bi) * SCALE;
}

// ---------------- Stage 4: cubic Lagrange from float4-packed table ----------
__device__ __forceinline__ float interp4(const float4* __restrict__ T,
                                         float th, float inv_h) {
    float t  = th * inv_h;
    float jf = floorf(t);
    float s  = t - jf;
    int j = (int)jf - 1;
    j = min(max(j, 0), TABLE_N);           // entries 0..TABLE_N

    float4 v = T[j];                        // one LDS.128: taps j..j+3
    float sm1 = s + 1.0f, s1 = s - 1.0f, s2 = s - 2.0f;
    float a = s * s1;
    float b = sm1 * s2;
    float w0 = -0.16666667f * (a * s2);
    float w1 =  0.5f        * (b * s1);
    float w2 = -0.5f        * (b * s);
    float w3 =  0.16666667f * (sm1 * a);
    return fmaf(w0, v.x, fmaf(w1, v.y, fmaf(w2, v.z, w3 * v.w)));
}

__global__ void __launch_bounds__(256) mie_main_kernel(
    const float* __restrict__ theta, float* __restrict__ out, int n)
{
    __shared__ float4 Ts4[TABLE_ENTRIES];   // 32.8 KB
    for (int i = threadIdx.x; i < TABLE_ENTRIES; i += 256)
        Ts4[i] = make_float4(g_table[i], g_table[i + 1],
                             g_table[i + 2], g_table[i + 3]);
    __syncthreads();

    const float INV_H = (float)TABLE_N / 3.14159265358979323846f;
    long long blockBase4 = (long long)blockIdx.x * (ELEMS_PER_BLOCK / 4);
    const float4* __restrict__ th4 = (const float4*)theta;
    float4* __restrict__ out4 = (float4*)out;

#pragma unroll
    for (int k = 0; k < 8; k++) {
        long long i4 = blockBase4 + k * 256 + threadIdx.x;
        long long e0 = i4 * 4;
        if (e0 + 3 < n) {
            float4 v = th4[i4];
            float4 r;
            r.x = interp4(Ts4, v.x, INV_H);
            r.y = interp4(Ts4, v.y, INV_H);
            r.z = interp4(Ts4, v.z, INV_H);
            r.w = interp4(Ts4, v.w, INV_H);
            out4[i4] = r;
        } else {
            for (long long e = e0; e < n && e < e0 + 4; e++)
                out[e] = interp4(Ts4, theta[e], INV_H);
        }
    }
}

// ---------------------------------------------------------------------------
extern "C" void kernel_launch(void* const* d_in, const int* in_sizes, int n_in,
                              void* d_out, int out_size) {
    const float* d     = (const float*)d_in[0];
    const float* theta = (const float*)d_in[1];
    float* out = (float*)d_out;
    int n = in_sizes[0];

    mie_reduce_kernel<<<RED_BLOCKS, RED_THREADS>>>(d, n);
    mie_coeff_kernel<<<1, 64>>>(n);
    mie_table_kernel<<<(TABLE_PTS + 255) / 256, 256>>>();
    int blocks = (n + ELEMS_PER_BLOCK - 1) / ELEMS_PER_BLOCK;
    mie_main_kernel<<<blocks, 256>>>(theta, out, n);
}